// round 1
// baseline (speedup 1.0000x reference)
#include <cuda_runtime.h>
#include <cstddef>

#define GH 1024
#define GW 1024
#define GC 32
#define GHW (GH * GW)

// 128 MB transposed params: [HW, C] so each grid cell's 32 channels are one
// contiguous, 128B-aligned block.
__device__ float g_params_t[(size_t)GHW * GC];

// ---------------------------------------------------------------------------
// Kernel 1: transpose [C, HW] -> [HW, C]. 32x32 fp32 tiles via padded smem.
// Both the global read (32 consecutive p per row) and the global write
// (32 consecutive c per point) are fully coalesced 128B transactions.
// ---------------------------------------------------------------------------
__global__ void transpose_kernel(const float* __restrict__ in) {
    __shared__ float tile[32][33];
    const int p0 = blockIdx.x * 32;
    const int tx = threadIdx.x;  // 0..31
    const int ty = threadIdx.y;  // 0..7

#pragma unroll
    for (int c = ty; c < 32; c += 8) {
        tile[c][tx] = in[(size_t)c * GHW + p0 + tx];
    }
    __syncthreads();
#pragma unroll
    for (int r = ty; r < 32; r += 8) {
        g_params_t[(size_t)(p0 + r) * GC + tx] = tile[tx][r];
    }
}

// ---------------------------------------------------------------------------
// Kernel 2: bilinear gather. 8 lanes cooperate on one point; each lane owns a
// float4 (4 channels). Per corner, the 8 lanes together read one full
// 128B-aligned line. Output store: 4 consecutive points per warp -> 512B of
// contiguous STG.128 per warp instruction.
// ---------------------------------------------------------------------------
__global__ void gather_kernel(const float* __restrict__ coord,
                              float* __restrict__ out,
                              int n_points) {
    const int t   = blockIdx.x * blockDim.x + threadIdx.x;
    const int p   = t >> 3;
    const int sub = t & 7;
    if (p >= n_points) return;

    const float2 xy = __ldg(((const float2*)coord) + p);

    // align_corners=True mapping, identical to the reference.
    const float ix = (xy.x + 1.0f) * 0.5f * (float)(GW - 1);
    const float iy = (xy.y + 1.0f) * 0.5f * (float)(GH - 1);

    const float fx0 = floorf(ix);
    const float fy0 = floorf(iy);
    const float wx1 = ix - fx0;           // = ix - ix0
    const float wy1 = iy - fy0;
    const float wx0 = 1.0f - wx1;         // = ix1 - ix   (ix1 = ix0 + 1, unclamped)
    const float wy0 = 1.0f - wy1;

    int x0 = (int)fx0; x0 = x0 < 0 ? 0 : (x0 > GW - 1 ? GW - 1 : x0);
    int y0 = (int)fy0; y0 = y0 < 0 ? 0 : (y0 > GH - 1 ? GH - 1 : y0);
    int x1 = x0 + 1;   x1 = x1 > GW - 1 ? GW - 1 : x1;
    int y1 = y0 + 1;   y1 = y1 > GH - 1 ? GH - 1 : y1;

    const float w_nw = wx0 * wy0;
    const float w_ne = wx1 * wy0;
    const float w_sw = wx0 * wy1;
    const float w_se = wx1 * wy1;

    const float4* __restrict__ base = (const float4*)g_params_t;
    const size_t row0 = (size_t)y0 * GW;
    const size_t row1 = (size_t)y1 * GW;

    const float4 v_nw = base[(row0 + x0) * 8 + sub];
    const float4 v_ne = base[(row0 + x1) * 8 + sub];
    const float4 v_sw = base[(row1 + x0) * 8 + sub];
    const float4 v_se = base[(row1 + x1) * 8 + sub];

    float4 o;
    o.x = v_nw.x * w_nw + v_ne.x * w_ne + v_sw.x * w_sw + v_se.x * w_se;
    o.y = v_nw.y * w_nw + v_ne.y * w_ne + v_sw.y * w_sw + v_se.y * w_se;
    o.z = v_nw.z * w_nw + v_ne.z * w_ne + v_sw.z * w_sw + v_se.z * w_se;
    o.w = v_nw.w * w_nw + v_ne.w * w_ne + v_sw.w * w_sw + v_se.w * w_se;

    ((float4*)out)[(size_t)p * 8 + sub] = o;
}

extern "C" void kernel_launch(void* const* d_in, const int* in_sizes, int n_in,
                              void* d_out, int out_size) {
    // Identify inputs by size for robustness: coord = 2M*2 = 4M elems,
    // params = 32*1024*1024 = 33.5M elems.
    const float* coord;
    const float* params;
    int coord_elems;
    if (in_sizes[0] < in_sizes[1]) {
        coord = (const float*)d_in[0];
        params = (const float*)d_in[1];
        coord_elems = in_sizes[0];
    } else {
        coord = (const float*)d_in[1];
        params = (const float*)d_in[0];
        coord_elems = in_sizes[1];
    }
    const int n_points = coord_elems / 2;

    // Kernel 1: transpose params into [HW, C] scratch.
    transpose_kernel<<<GHW / 32, dim3(32, 8)>>>(params);

    // Kernel 2: bilinear gather, 8 lanes per point.
    const int total_threads = n_points * 8;
    const int block = 256;
    const int grid = (total_threads + block - 1) / block;
    gather_kernel<<<grid, block>>>(coord, (float*)d_out, n_points);
}

// round 2
// speedup vs baseline: 1.1626x; 1.1626x over previous
#include <cuda_runtime.h>
#include <cstddef>

#define GH 1024
#define GW 1024
#define GC 32
#define GHW (GH * GW)

// 128 MB transposed params: [HW, C] so each grid cell's 32 channels are one
// contiguous, 128B-aligned block.
__device__ float g_params_t[(size_t)GHW * GC];

// ---------------------------------------------------------------------------
// Kernel 1: transpose [C, HW] -> [HW, C]. 32 channels x 128 points per block,
// float4 on both the load and store sides. Smem tile stride 129 floats makes
// the store-side gather (tile[4j+k][p]) conflict-free: bank = (4j+k+p) % 32,
// and {4j+p} covers 0..31 exactly once per warp.
// ---------------------------------------------------------------------------
__global__ void transpose_kernel(const float* __restrict__ in) {
    __shared__ float tile[32][129];
    const int p0 = blockIdx.x * 128;
    const int tx = threadIdx.x;  // 0..31
    const int ty = threadIdx.y;  // 0..7

    // Load: 32 rows of 128 floats, each row = 32 float4 (one per tx).
#pragma unroll
    for (int c = ty; c < 32; c += 8) {
        const float4 v = __ldg((const float4*)(in + (size_t)c * GHW + p0) + tx);
        tile[c][tx * 4 + 0] = v.x;
        tile[c][tx * 4 + 1] = v.y;
        tile[c][tx * 4 + 2] = v.z;
        tile[c][tx * 4 + 3] = v.w;
    }
    __syncthreads();

    // Store: 128 points x 8 float4 each = 1024 float4, 4 iters of 256 threads.
    const int t = ty * 32 + tx;
    float4* __restrict__ outv = (float4*)(g_params_t + (size_t)p0 * GC);
#pragma unroll
    for (int i = 0; i < 4; i++) {
        const int f = i * 256 + t;
        const int p = f >> 3;
        const int j = f & 7;
        float4 v;
        v.x = tile[4 * j + 0][p];
        v.y = tile[4 * j + 1][p];
        v.z = tile[4 * j + 2][p];
        v.w = tile[4 * j + 3][p];
        outv[p * 8 + j] = v;  // default (evict-normal): keep resident for gather
    }
}

// ---------------------------------------------------------------------------
// Kernel 2: bilinear gather. 8 lanes cooperate on one point; each lane owns a
// float4 (4 channels). Per corner, the 8 lanes together read one full
// 128B-aligned line. Output stores use .cs (evict-first) so the 256MB
// streaming output does not evict the 128MB params working set from L2.
// ---------------------------------------------------------------------------
__global__ void gather_kernel(const float* __restrict__ coord,
                              float* __restrict__ out,
                              int n_points) {
    const int t   = blockIdx.x * blockDim.x + threadIdx.x;
    const int p   = t >> 3;
    const int sub = t & 7;
    if (p >= n_points) return;

    const float2 xy = __ldcs(((const float2*)coord) + p);

    // align_corners=True mapping, identical to the reference.
    const float ix = (xy.x + 1.0f) * 0.5f * (float)(GW - 1);
    const float iy = (xy.y + 1.0f) * 0.5f * (float)(GH - 1);

    const float fx0 = floorf(ix);
    const float fy0 = floorf(iy);
    const float wx1 = ix - fx0;           // = ix - ix0
    const float wy1 = iy - fy0;
    const float wx0 = 1.0f - wx1;         // = ix1 - ix   (ix1 = ix0 + 1, unclamped)
    const float wy0 = 1.0f - wy1;

    int x0 = (int)fx0; x0 = x0 < 0 ? 0 : (x0 > GW - 1 ? GW - 1 : x0);
    int y0 = (int)fy0; y0 = y0 < 0 ? 0 : (y0 > GH - 1 ? GH - 1 : y0);
    int x1 = x0 + 1;   x1 = x1 > GW - 1 ? GW - 1 : x1;
    int y1 = y0 + 1;   y1 = y1 > GH - 1 ? GH - 1 : y1;

    const float w_nw = wx0 * wy0;
    const float w_ne = wx1 * wy0;
    const float w_sw = wx0 * wy1;
    const float w_se = wx1 * wy1;

    const float4* __restrict__ base = (const float4*)g_params_t;
    const size_t row0 = (size_t)y0 * GW;
    const size_t row1 = (size_t)y1 * GW;

    const float4 v_nw = __ldg(base + (row0 + x0) * 8 + sub);
    const float4 v_ne = __ldg(base + (row0 + x1) * 8 + sub);
    const float4 v_sw = __ldg(base + (row1 + x0) * 8 + sub);
    const float4 v_se = __ldg(base + (row1 + x1) * 8 + sub);

    float4 o;
    o.x = v_nw.x * w_nw + v_ne.x * w_ne + v_sw.x * w_sw + v_se.x * w_se;
    o.y = v_nw.y * w_nw + v_ne.y * w_ne + v_sw.y * w_sw + v_se.y * w_se;
    o.z = v_nw.z * w_nw + v_ne.z * w_ne + v_sw.z * w_sw + v_se.z * w_se;
    o.w = v_nw.w * w_nw + v_ne.w * w_ne + v_sw.w * w_sw + v_se.w * w_se;

    // Streaming store: evict-first, don't pollute L2.
    __stcs(((float4*)out) + (size_t)p * 8 + sub, o);
}

extern "C" void kernel_launch(void* const* d_in, const int* in_sizes, int n_in,
                              void* d_out, int out_size) {
    // Identify inputs by size: coord = 4M elems, params = 33.5M elems.
    const float* coord;
    const float* params;
    int coord_elems;
    if (in_sizes[0] < in_sizes[1]) {
        coord = (const float*)d_in[0];
        params = (const float*)d_in[1];
        coord_elems = in_sizes[0];
    } else {
        coord = (const float*)d_in[1];
        params = (const float*)d_in[0];
        coord_elems = in_sizes[1];
    }
    const int n_points = coord_elems / 2;

    // Kernel 1: transpose params into [HW, C] scratch (float4 both sides).
    transpose_kernel<<<GHW / 128, dim3(32, 8)>>>(params);

    // Kernel 2: bilinear gather, 8 lanes per point.
    const int total_threads = n_points * 8;
    const int block = 256;
    const int grid = (total_threads + block - 1) / block;
    gather_kernel<<<grid, block>>>(coord, (float*)d_out, n_points);
}

// round 3
// speedup vs baseline: 1.4620x; 1.2575x over previous
#include <cuda_runtime.h>
#include <cuda_fp16.h>
#include <cstddef>

#define GH 1024
#define GW 1024
#define GC 32
#define GHW (GH * GW)

// 64 MB transposed fp16 params: [HW, C]. Each grid cell's 32 channels are one
// contiguous 64B block. Working set now fits L2 (126 MB) during the gather.
__device__ __half g_params_h[(size_t)GHW * GC];

// ---------------------------------------------------------------------------
// Kernel 1: transpose + convert. [C, HW] fp32 -> [HW, C] fp16.
// 32 channels x 128 points per block. float4 loads, half2 stores (128B
// contiguous per 2 points across a warp).
// ---------------------------------------------------------------------------
__global__ void transpose_kernel(const float* __restrict__ in) {
    __shared__ float tile[32][129];
    const int p0 = blockIdx.x * 128;
    const int tx = threadIdx.x;  // 0..31
    const int ty = threadIdx.y;  // 0..7

#pragma unroll
    for (int c = ty; c < 32; c += 8) {
        const float4 v = __ldg((const float4*)(in + (size_t)c * GHW + p0) + tx);
        tile[c][tx * 4 + 0] = v.x;
        tile[c][tx * 4 + 1] = v.y;
        tile[c][tx * 4 + 2] = v.z;
        tile[c][tx * 4 + 3] = v.w;
    }
    __syncthreads();

    // 128 points x 16 half2 each = 2048 half2; 256 threads x 8 iters.
    const int t = ty * 32 + tx;
    __half2* __restrict__ outv = (__half2*)(g_params_h + (size_t)p0 * GC);
#pragma unroll
    for (int i = 0; i < 8; i++) {
        const int f = i * 256 + t;
        const int p = f >> 4;       // point within tile
        const int j = f & 15;       // half2 index (channels 2j, 2j+1)
        outv[p * 16 + j] = __floats2half2_rn(tile[2 * j][p], tile[2 * j + 1][p]);
    }
}

// ---------------------------------------------------------------------------
// Kernel 2: bilinear gather from fp16 [HW, C]. 8 lanes per point; each lane
// owns 4 channels: one uint2 (4 halves) load per corner, fp32 accumulation,
// one float4 store. Warp output stores are 512B fully contiguous.
// ---------------------------------------------------------------------------
__global__ void gather_kernel(const float* __restrict__ coord,
                              float* __restrict__ out,
                              int n_points) {
    const int t   = blockIdx.x * blockDim.x + threadIdx.x;
    const int p   = t >> 3;
    const int sub = t & 7;
    if (p >= n_points) return;

    const float2 xy = __ldcs(((const float2*)coord) + p);

    // align_corners=True mapping, identical to the reference.
    const float ix = (xy.x + 1.0f) * 0.5f * (float)(GW - 1);
    const float iy = (xy.y + 1.0f) * 0.5f * (float)(GH - 1);

    const float fx0 = floorf(ix);
    const float fy0 = floorf(iy);
    const float wx1 = ix - fx0;
    const float wy1 = iy - fy0;
    const float wx0 = 1.0f - wx1;
    const float wy0 = 1.0f - wy1;

    int x0 = (int)fx0; x0 = x0 < 0 ? 0 : (x0 > GW - 1 ? GW - 1 : x0);
    int y0 = (int)fy0; y0 = y0 < 0 ? 0 : (y0 > GH - 1 ? GH - 1 : y0);
    int x1 = x0 + 1;   x1 = x1 > GW - 1 ? GW - 1 : x1;
    int y1 = y0 + 1;   y1 = y1 > GH - 1 ? GH - 1 : y1;

    const float w_nw = wx0 * wy0;
    const float w_ne = wx1 * wy0;
    const float w_sw = wx0 * wy1;
    const float w_se = wx1 * wy1;

    // 8 uint2 (= 32 halves) per grid cell.
    const uint2* __restrict__ base = (const uint2*)g_params_h;
    const size_t c_nw = ((size_t)y0 * GW + x0) * 8 + sub;
    const size_t c_ne = ((size_t)y0 * GW + x1) * 8 + sub;
    const size_t c_sw = ((size_t)y1 * GW + x0) * 8 + sub;
    const size_t c_se = ((size_t)y1 * GW + x1) * 8 + sub;

    const uint2 r_nw = __ldg(base + c_nw);
    const uint2 r_ne = __ldg(base + c_ne);
    const uint2 r_sw = __ldg(base + c_sw);
    const uint2 r_se = __ldg(base + c_se);

    float4 o;
    {
        const float2 a0 = __half22float2(*(const __half2*)&r_nw.x);
        const float2 b0 = __half22float2(*(const __half2*)&r_ne.x);
        const float2 c0 = __half22float2(*(const __half2*)&r_sw.x);
        const float2 d0 = __half22float2(*(const __half2*)&r_se.x);
        o.x = a0.x * w_nw + b0.x * w_ne + c0.x * w_sw + d0.x * w_se;
        o.y = a0.y * w_nw + b0.y * w_ne + c0.y * w_sw + d0.y * w_se;
        const float2 a1 = __half22float2(*(const __half2*)&r_nw.y);
        const float2 b1 = __half22float2(*(const __half2*)&r_ne.y);
        const float2 c1 = __half22float2(*(const __half2*)&r_sw.y);
        const float2 d1 = __half22float2(*(const __half2*)&r_se.y);
        o.z = a1.x * w_nw + b1.x * w_ne + c1.x * w_sw + d1.x * w_se;
        o.w = a1.y * w_nw + b1.y * w_ne + c1.y * w_sw + d1.y * w_se;
    }

    // Streaming store: evict-first, keep params resident in L2.
    __stcs(((float4*)out) + (size_t)p * 8 + sub, o);
}

extern "C" void kernel_launch(void* const* d_in, const int* in_sizes, int n_in,
                              void* d_out, int out_size) {
    const float* coord;
    const float* params;
    int coord_elems;
    if (in_sizes[0] < in_sizes[1]) {
        coord = (const float*)d_in[0];
        params = (const float*)d_in[1];
        coord_elems = in_sizes[0];
    } else {
        coord = (const float*)d_in[1];
        params = (const float*)d_in[0];
        coord_elems = in_sizes[1];
    }
    const int n_points = coord_elems / 2;

    transpose_kernel<<<GHW / 128, dim3(32, 8)>>>(params);

    const int total_threads = n_points * 8;
    const int block = 256;
    const int grid = (total_threads + block - 1) / block;
    gather_kernel<<<grid, block>>>(coord, (float*)d_out, n_points);
}

// round 4
// speedup vs baseline: 1.6852x; 1.1526x over previous
#include <cuda_runtime.h>
#include <cuda_fp16.h>
#include <cstddef>

#define GH 1024
#define GW 1024
#define GC 32
#define GHW (GH * GW)

// 64 MB transposed fp16 params: [HW, C]. Each grid cell's 32 channels are one
// contiguous 64B block. Working set fits L2 (126 MB) during the gather.
__device__ __half g_params_h[(size_t)GHW * GC];

// ---------------------------------------------------------------------------
// Kernel 1: transpose + convert. [C, HW] fp32 -> [HW, C] fp16.
// 32 channels x 128 points per block. float4 streaming loads (.cs — read
// once), half2 stores (contiguous across the warp).
// ---------------------------------------------------------------------------
__global__ void transpose_kernel(const float* __restrict__ in) {
    __shared__ float tile[32][129];
    const int p0 = blockIdx.x * 128;
    const int tx = threadIdx.x;  // 0..31
    const int ty = threadIdx.y;  // 0..7

#pragma unroll
    for (int c = ty; c < 32; c += 8) {
        const float4 v = __ldcs((const float4*)(in + (size_t)c * GHW + p0) + tx);
        tile[c][tx * 4 + 0] = v.x;
        tile[c][tx * 4 + 1] = v.y;
        tile[c][tx * 4 + 2] = v.z;
        tile[c][tx * 4 + 3] = v.w;
    }
    __syncthreads();

    // 128 points x 16 half2 each = 2048 half2; 256 threads x 8 iters.
    const int t = ty * 32 + tx;
    __half2* __restrict__ outv = (__half2*)(g_params_h + (size_t)p0 * GC);
#pragma unroll
    for (int i = 0; i < 8; i++) {
        const int f = i * 256 + t;
        const int p = f >> 4;       // point within tile
        const int j = f & 15;       // half2 index (channels 2j, 2j+1)
        outv[p * 16 + j] = __floats2half2_rn(tile[2 * j][p], tile[2 * j + 1][p]);
    }
}

// ---------------------------------------------------------------------------
// Kernel 2: bilinear gather from fp16 [HW, C]. 4 lanes per point; each lane
// owns 8 channels: one uint4 (16B) LDG.128 per corner -> 4 independent 16B
// loads in flight per thread. fp32 accumulation, two float4 stores.
// ---------------------------------------------------------------------------
__global__ void gather_kernel(const float* __restrict__ coord,
                              float* __restrict__ out,
                              int n_points) {
    const int t   = blockIdx.x * blockDim.x + threadIdx.x;
    const int p   = t >> 2;
    const int sub = t & 3;          // 8 channels per lane: 8*sub .. 8*sub+7
    if (p >= n_points) return;

    const float2 xy = __ldg(((const float2*)coord) + p);

    // align_corners=True mapping, identical to the reference.
    const float ix = (xy.x + 1.0f) * 0.5f * (float)(GW - 1);
    const float iy = (xy.y + 1.0f) * 0.5f * (float)(GH - 1);

    const float fx0 = floorf(ix);
    const float fy0 = floorf(iy);
    const float wx1 = ix - fx0;
    const float wy1 = iy - fy0;
    const float wx0 = 1.0f - wx1;
    const float wy0 = 1.0f - wy1;

    int x0 = (int)fx0; x0 = x0 < 0 ? 0 : (x0 > GW - 1 ? GW - 1 : x0);
    int y0 = (int)fy0; y0 = y0 < 0 ? 0 : (y0 > GH - 1 ? GH - 1 : y0);
    int x1 = x0 + 1;   x1 = x1 > GW - 1 ? GW - 1 : x1;
    int y1 = y0 + 1;   y1 = y1 > GH - 1 ? GH - 1 : y1;

    const float w_nw = wx0 * wy0;
    const float w_ne = wx1 * wy0;
    const float w_sw = wx0 * wy1;
    const float w_se = wx1 * wy1;

    // 4 uint4 (= 32 halves) per grid cell.
    const uint4* __restrict__ base = (const uint4*)g_params_h;
    const uint4 r_nw = __ldg(base + ((size_t)y0 * GW + x0) * 4 + sub);
    const uint4 r_ne = __ldg(base + ((size_t)y0 * GW + x1) * 4 + sub);
    const uint4 r_sw = __ldg(base + ((size_t)y1 * GW + x0) * 4 + sub);
    const uint4 r_se = __ldg(base + ((size_t)y1 * GW + x1) * 4 + sub);

    float o[8];
#pragma unroll
    for (int h = 0; h < 4; h++) {
        const unsigned ua = (&r_nw.x)[h];
        const unsigned ub = (&r_ne.x)[h];
        const unsigned uc = (&r_sw.x)[h];
        const unsigned ud = (&r_se.x)[h];
        const float2 a = __half22float2(*(const __half2*)&ua);
        const float2 b = __half22float2(*(const __half2*)&ub);
        const float2 c = __half22float2(*(const __half2*)&uc);
        const float2 d = __half22float2(*(const __half2*)&ud);
        o[2 * h + 0] = a.x * w_nw + b.x * w_ne + c.x * w_sw + d.x * w_se;
        o[2 * h + 1] = a.y * w_nw + b.y * w_ne + c.y * w_sw + d.y * w_se;
    }

    // Streaming stores: evict-first, keep params resident in L2.
    float4* __restrict__ ov = ((float4*)out) + (size_t)p * 8 + 2 * sub;
    __stcs(ov + 0, make_float4(o[0], o[1], o[2], o[3]));
    __stcs(ov + 1, make_float4(o[4], o[5], o[6], o[7]));
}

extern "C" void kernel_launch(void* const* d_in, const int* in_sizes, int n_in,
                              void* d_out, int out_size) {
    const float* coord;
    const float* params;
    int coord_elems;
    if (in_sizes[0] < in_sizes[1]) {
        coord = (const float*)d_in[0];
        params = (const float*)d_in[1];
        coord_elems = in_sizes[0];
    } else {
        coord = (const float*)d_in[1];
        params = (const float*)d_in[0];
        coord_elems = in_sizes[1];
    }
    const int n_points = coord_elems / 2;

    transpose_kernel<<<GHW / 128, dim3(32, 8)>>>(params);

    const int total_threads = n_points * 4;
    const int block = 256;
    const int grid = (total_threads + block - 1) / block;
    gather_kernel<<<grid, block>>>(coord, (float*)d_out, n_points);
}